// round 1
// baseline (speedup 1.0000x reference)
#include <cuda_runtime.h>

#define NN 50000
#define RR 4
#define EE 400000

// ---- scratch (static __device__; no allocation) ----
__device__ float g_P [NN * 256];   // [N][2*Do] basis projections (P0 | P1)
__device__ float g_h1[NN * 128];   // layer-0 output (pre-relu)
__device__ float g_h2[NN * 128];   // layer-1 output (pre-relu)
__device__ int   g_deg [8 * NN];   // [out:4][N] then [in:4][N]
__device__ float g_norm[8 * NN];   // rsqrt(max(deg,1)) same layout

// ---------------- utility kernels ----------------
__global__ void k_zero4(float* __restrict__ p, int n4) {
    float4 z = make_float4(0.f, 0.f, 0.f, 0.f);
    for (int i = blockIdx.x * blockDim.x + threadIdx.x; i < n4;
         i += gridDim.x * blockDim.x)
        ((float4*)p)[i] = z;
}

__global__ void k_count(const int* __restrict__ src, const int* __restrict__ dst) {
    int i = blockIdx.x * blockDim.x + threadIdx.x;
    if (i >= RR * EE) return;
    int r = i / EE;
    atomicAdd(&g_deg[r * NN + src[i]], 1);            // out-degree
    atomicAdd(&g_deg[4 * NN + r * NN + dst[i]], 1);   // in-degree
}

__global__ void k_norm() {
    int i = blockIdx.x * blockDim.x + threadIdx.x;
    if (i < 8 * NN) {
        int d = g_deg[i];
        if (d < 1) d = 1;
        g_norm[i] = rsqrtf((float)d);
    }
}

// ---------------- fused 2-basis GEMM ----------------
// Pout[n][b*Do+o] = sum_k relu?(H[n][k]) * Bmat[b][k][o]   (WOUT = 2*Do)
template<int WOUT, bool RELU>
__global__ void __launch_bounds__(256)
k_gemm(const float* __restrict__ Hm, const float* __restrict__ Bmat,
       float* __restrict__ Pout, int n) {
    const int Do = WOUT / 2;
    const int NJ = WOUT / 32;
    __shared__ float As[32][33];
    __shared__ float Bs[32 * WOUT];

    int row0 = blockIdx.x * 32;
    int tid  = threadIdx.x;
    int tx   = tid & 31;
    int ty   = tid >> 5;

    float acc[4][NJ];
#pragma unroll
    for (int i = 0; i < 4; i++)
#pragma unroll
        for (int j = 0; j < NJ; j++) acc[i][j] = 0.f;

    for (int k0 = 0; k0 < 128; k0 += 32) {
        // stage A tile [32 rows x 32 k]
        for (int idx = tid; idx < 32 * 32; idx += 256) {
            int r = idx >> 5, k = idx & 31;
            int row = row0 + r;
            float v = (row < n) ? Hm[row * 128 + k0 + k] : 0.f;
            if (RELU) v = fmaxf(v, 0.f);
            As[r][k] = v;
        }
        // stage B tile [32 k x WOUT] (both bases side by side)
        for (int idx = tid; idx < 32 * WOUT; idx += 256) {
            int k = idx / WOUT, c = idx % WOUT;
            int b = c / Do,    o = c % Do;
            Bs[idx] = Bmat[b * 128 * Do + (k0 + k) * Do + o];
        }
        __syncthreads();
#pragma unroll 8
        for (int k = 0; k < 32; k++) {
            float a[4];
#pragma unroll
            for (int i = 0; i < 4; i++) a[i] = As[ty + 8 * i][k];
#pragma unroll
            for (int j = 0; j < NJ; j++) {
                float b = Bs[k * WOUT + tx + 32 * j];
#pragma unroll
                for (int i = 0; i < 4; i++) acc[i][j] = fmaf(a[i], b, acc[i][j]);
            }
        }
        __syncthreads();
    }
#pragma unroll
    for (int i = 0; i < 4; i++) {
        int row = row0 + ty + 8 * i;
        if (row < n) {
#pragma unroll
            for (int j = 0; j < NJ; j++)
                Pout[row * WOUT + tx + 32 * j] = acc[i][j];
        }
    }
}

// ---------------- edge gather / scatter-add ----------------
__device__ __forceinline__ void red4(float* a, float4 v) {
    asm volatile("red.global.add.v4.f32 [%0], {%1,%2,%3,%4};"
                 :: "l"(a), "f"(v.x), "f"(v.y), "f"(v.z), "f"(v.w) : "memory");
}
__device__ __forceinline__ void red2(float* a, float2 v) {
    asm volatile("red.global.add.v2.f32 [%0], {%1,%2};"
                 :: "l"(a), "f"(v.x), "f"(v.y) : "memory");
}

// one warp per edge: out[dst] += n_in[r][dst]*n_out[r][src]*(c_r0*P0[src]+c_r1*P1[src])
template<int DO>
__global__ void __launch_bounds__(256)
k_edge(const float* __restrict__ Pm, const int* __restrict__ src,
       const int* __restrict__ dst, const float* __restrict__ coeff,
       const float* __restrict__ norm, float* __restrict__ outp) {
    long long t = (long long)blockIdx.x * blockDim.x + threadIdx.x;
    int gw   = (int)(t >> 5);
    int lane = threadIdx.x & 31;
    if (gw >= RR * EE) return;
    int r = gw / EE;
    int s = src[gw];
    int d = dst[gw];
    float a  = norm[r * NN + s] * norm[4 * NN + r * NN + d];
    float w0 = a * coeff[2 * r];
    float w1 = a * coeff[2 * r + 1];
    const float* prow = Pm + s * (2 * DO);
    if (DO == 128) {
        float4 x0 = ((const float4*)prow)[lane];
        float4 x1 = ((const float4*)(prow + DO))[lane];
        float4 v;
        v.x = w0 * x0.x + w1 * x1.x;
        v.y = w0 * x0.y + w1 * x1.y;
        v.z = w0 * x0.z + w1 * x1.z;
        v.w = w0 * x0.w + w1 * x1.w;
        red4(outp + d * DO + lane * 4, v);
    } else {
        float2 x0 = ((const float2*)prow)[lane];
        float2 x1 = ((const float2*)(prow + DO))[lane];
        float2 v;
        v.x = w0 * x0.x + w1 * x1.x;
        v.y = w0 * x0.y + w1 * x1.y;
        red2(outp + d * DO + lane * 2, v);
    }
}

// ---------------- launch ----------------
extern "C" void kernel_launch(void* const* d_in, const int* in_sizes, int n_in,
                              void* d_out, int out_size) {
    const float* x   = (const float*)d_in[0];
    const int*   src = (const int*)  d_in[1];
    const int*   dst = (const int*)  d_in[2];
    const float* b0  = (const float*)d_in[3];
    const float* c0  = (const float*)d_in[4];
    const float* b1  = (const float*)d_in[5];
    const float* c1  = (const float*)d_in[6];
    const float* b2  = (const float*)d_in[7];
    const float* c2  = (const float*)d_in[8];
    float* out = (float*)d_out;

    float *P, *h1, *h2, *nrm; int* deg;
    cudaGetSymbolAddress((void**)&P,   g_P);
    cudaGetSymbolAddress((void**)&h1,  g_h1);
    cudaGetSymbolAddress((void**)&h2,  g_h2);
    cudaGetSymbolAddress((void**)&deg, g_deg);
    cudaGetSymbolAddress((void**)&nrm, g_norm);

    const int edgeBlocks = (RR * EE * 32 + 255) / 256;   // one warp per edge
    const int gemmGrid   = (NN + 31) / 32;

    // degrees + norms (recomputed every call: deterministic, no caching)
    k_zero4<<<512, 256>>>((float*)deg, (8 * NN) / 4);
    k_count<<<(RR * EE + 255) / 256, 256>>>(src, dst);
    k_norm<<<(8 * NN + 255) / 256, 256>>>();

    // layer 0: x -> h1 (relu deferred to layer-1 GEMM load)
    k_gemm<256, false><<<gemmGrid, 256>>>(x, b0, P, NN);
    k_zero4<<<2048, 256>>>(h1, NN * 128 / 4);
    k_edge<128><<<edgeBlocks, 256>>>(P, src, dst, c0, nrm, h1);

    // layer 1: relu(h1) -> h2
    k_gemm<256, true><<<gemmGrid, 256>>>(h1, b1, P, NN);
    k_zero4<<<2048, 256>>>(h2, NN * 128 / 4);
    k_edge<128><<<edgeBlocks, 256>>>(P, src, dst, c1, nrm, h2);

    // layer 2: relu(h2) -> out (no final activation)
    k_gemm<128, true><<<gemmGrid, 256>>>(h2, b2, P, NN);
    k_zero4<<<2048, 256>>>(out, NN * 64 / 4);
    k_edge<64><<<edgeBlocks, 256>>>(P, src, dst, c2, nrm, out);
}

// round 2
// speedup vs baseline: 1.1666x; 1.1666x over previous
#include <cuda_runtime.h>
#include <cuda_fp16.h>

#define NN 50000
#define RR 4
#define EE 400000

// ---- scratch (static __device__; no allocation) ----
__device__ __half2 g_P [NN * 128];  // interleaved pairs (P0[o],P1[o]); max DO=128
__device__ float   g_h1[NN * 128];  // layer-0 output (pre-relu)
__device__ float   g_h2[NN * 128];  // layer-1 output (pre-relu)
__device__ int     g_deg [8 * NN];  // [out:4][N] then [in:4][N]
__device__ float   g_norm[8 * NN];  // rsqrt(max(deg,1)) same layout

// ---------------- utility kernels ----------------
__global__ void k_zero4(float* __restrict__ p, int n4) {
    float4 z = make_float4(0.f, 0.f, 0.f, 0.f);
    for (int i = blockIdx.x * blockDim.x + threadIdx.x; i < n4;
         i += gridDim.x * blockDim.x)
        ((float4*)p)[i] = z;
}

__global__ void k_count(const int* __restrict__ src, const int* __restrict__ dst) {
    int i = blockIdx.x * blockDim.x + threadIdx.x;
    if (i >= RR * EE) return;
    int r = i / EE;
    atomicAdd(&g_deg[r * NN + src[i]], 1);            // out-degree
    atomicAdd(&g_deg[4 * NN + r * NN + dst[i]], 1);   // in-degree
}

__global__ void k_norm() {
    int i = blockIdx.x * blockDim.x + threadIdx.x;
    if (i < 8 * NN) {
        int d = g_deg[i];
        if (d < 1) d = 1;
        g_norm[i] = rsqrtf((float)d);
    }
}

// ---------------- fused 2-basis GEMM, fp16 interleaved output ----------------
// Pout[n][o] = half2( sum_k A[n][k]*B0[k][o], sum_k A[n][k]*B1[k][o] )
template<int DO, bool RELU>
__global__ void __launch_bounds__(256)
k_gemm(const float* __restrict__ Hm, const float* __restrict__ Bmat,
       __half2* __restrict__ Pout, int n) {
    const int W2 = 2 * DO;
    const int NJ = DO / 32;
    __shared__ float As[64][33];
    __shared__ float Bs[32 * W2];   // layout [k][2*o+b]

    int row0 = blockIdx.x * 64;
    int tid  = threadIdx.x;
    int tx   = tid & 31;
    int ty   = tid >> 5;

    float acc0[8][NJ], acc1[8][NJ];
#pragma unroll
    for (int i = 0; i < 8; i++)
#pragma unroll
        for (int j = 0; j < NJ; j++) { acc0[i][j] = 0.f; acc1[i][j] = 0.f; }

    for (int k0 = 0; k0 < 128; k0 += 32) {
        // stage A tile [64 rows x 32 k]
#pragma unroll
        for (int idx = tid; idx < 64 * 32; idx += 256) {
            int r = idx >> 5, k = idx & 31;
            int row = row0 + r;
            float v = (row < n) ? Hm[row * 128 + k0 + k] : 0.f;
            if (RELU) v = fmaxf(v, 0.f);
            As[r][k] = v;
        }
        // stage B tile [32 k x 2*DO] interleaved by basis
#pragma unroll
        for (int idx = tid; idx < 32 * W2; idx += 256) {
            int k = idx / W2, c = idx % W2;
            int o = c >> 1, b = c & 1;
            Bs[idx] = Bmat[(b * 128 + (k0 + k)) * DO + o];
        }
        __syncthreads();
#pragma unroll 4
        for (int k = 0; k < 32; k++) {
            float a[8];
#pragma unroll
            for (int i = 0; i < 8; i++) a[i] = As[ty * 8 + i][k];
#pragma unroll
            for (int j = 0; j < NJ; j++) {
                float2 bp = *(const float2*)&Bs[k * W2 + (tx + 32 * j) * 2];
#pragma unroll
                for (int i = 0; i < 8; i++) {
                    acc0[i][j] = fmaf(a[i], bp.x, acc0[i][j]);
                    acc1[i][j] = fmaf(a[i], bp.y, acc1[i][j]);
                }
            }
        }
        __syncthreads();
    }
#pragma unroll
    for (int i = 0; i < 8; i++) {
        int row = row0 + ty * 8 + i;
        if (row < n) {
#pragma unroll
            for (int j = 0; j < NJ; j++)
                Pout[row * DO + tx + 32 * j] =
                    __floats2half2_rn(acc0[i][j], acc1[i][j]);
        }
    }
}

// ---------------- edge gather / scatter-add ----------------
__device__ __forceinline__ void red4(float* a, float4 v) {
    asm volatile("red.global.add.v4.f32 [%0], {%1,%2,%3,%4};"
                 :: "l"(a), "f"(v.x), "f"(v.y), "f"(v.z), "f"(v.w) : "memory");
}
__device__ __forceinline__ void red2(float* a, float2 v) {
    asm volatile("red.global.add.v2.f32 [%0], {%1,%2};"
                 :: "l"(a), "f"(v.x), "f"(v.y) : "memory");
}

// one warp per edge: out[dst] += n_in[r][dst]*n_out[r][src]*(c_r0*P0[src]+c_r1*P1[src])
__global__ void __launch_bounds__(256)
k_edge128(const __half2* __restrict__ Pm, const int* __restrict__ src,
          const int* __restrict__ dst, const float* __restrict__ coeff,
          const float* __restrict__ norm, float* __restrict__ outp) {
    long long t = (long long)blockIdx.x * blockDim.x + threadIdx.x;
    int gw   = (int)(t >> 5);
    int lane = threadIdx.x & 31;
    if (gw >= RR * EE) return;
    int r = gw / EE;
    int s = src[gw];
    int d = dst[gw];
    float a  = norm[r * NN + s] * norm[4 * NN + r * NN + d];
    float w0 = a * coeff[2 * r];
    float w1 = a * coeff[2 * r + 1];
    uint4 pk = ((const uint4*)(Pm + s * 128))[lane];   // 8 halves = 4 (P0,P1) pairs
    const __half2* hp = (const __half2*)&pk;
    float2 f0 = __half22float2(hp[0]);
    float2 f1 = __half22float2(hp[1]);
    float2 f2 = __half22float2(hp[2]);
    float2 f3 = __half22float2(hp[3]);
    float4 v;
    v.x = w0 * f0.x + w1 * f0.y;
    v.y = w0 * f1.x + w1 * f1.y;
    v.z = w0 * f2.x + w1 * f2.y;
    v.w = w0 * f3.x + w1 * f3.y;
    red4(outp + d * 128 + lane * 4, v);
}

__global__ void __launch_bounds__(256)
k_edge64(const __half2* __restrict__ Pm, const int* __restrict__ src,
         const int* __restrict__ dst, const float* __restrict__ coeff,
         const float* __restrict__ norm, float* __restrict__ outp) {
    long long t = (long long)blockIdx.x * blockDim.x + threadIdx.x;
    int gw   = (int)(t >> 5);
    int lane = threadIdx.x & 31;
    if (gw >= RR * EE) return;
    int r = gw / EE;
    int s = src[gw];
    int d = dst[gw];
    float a  = norm[r * NN + s] * norm[4 * NN + r * NN + d];
    float w0 = a * coeff[2 * r];
    float w1 = a * coeff[2 * r + 1];
    uint2 pk = ((const uint2*)(Pm + s * 64))[lane];    // 4 halves = 2 pairs
    const __half2* hp = (const __half2*)&pk;
    float2 f0 = __half22float2(hp[0]);
    float2 f1 = __half22float2(hp[1]);
    float2 v;
    v.x = w0 * f0.x + w1 * f0.y;
    v.y = w0 * f1.x + w1 * f1.y;
    red2(outp + d * 64 + lane * 2, v);
}

// ---------------- launch ----------------
extern "C" void kernel_launch(void* const* d_in, const int* in_sizes, int n_in,
                              void* d_out, int out_size) {
    const float* x   = (const float*)d_in[0];
    const int*   src = (const int*)  d_in[1];
    const int*   dst = (const int*)  d_in[2];
    const float* b0  = (const float*)d_in[3];
    const float* c0  = (const float*)d_in[4];
    const float* b1  = (const float*)d_in[5];
    const float* c1  = (const float*)d_in[6];
    const float* b2  = (const float*)d_in[7];
    const float* c2  = (const float*)d_in[8];
    float* out = (float*)d_out;

    __half2* P; float *h1, *h2, *nrm; int* deg;
    cudaGetSymbolAddress((void**)&P,   g_P);
    cudaGetSymbolAddress((void**)&h1,  g_h1);
    cudaGetSymbolAddress((void**)&h2,  g_h2);
    cudaGetSymbolAddress((void**)&deg, g_deg);
    cudaGetSymbolAddress((void**)&nrm, g_norm);

    const int edgeBlocks = (RR * EE * 32 + 255) / 256;   // one warp per edge
    const int gemmGrid   = (NN + 63) / 64;

    // degrees + norms (recomputed every call: deterministic, no caching)
    k_zero4<<<512, 256>>>((float*)deg, (8 * NN) / 4);
    k_count<<<(RR * EE + 255) / 256, 256>>>(src, dst);
    k_norm<<<(8 * NN + 255) / 256, 256>>>();

    // layer 0: x -> h1 (relu deferred to layer-1 GEMM load)
    k_gemm<128, false><<<gemmGrid, 256>>>(x, b0, P, NN);
    k_zero4<<<2048, 256>>>(h1, NN * 128 / 4);
    k_edge128<<<edgeBlocks, 256>>>(P, src, dst, c0, nrm, h1);

    // layer 1: relu(h1) -> h2
    k_gemm<128, true><<<gemmGrid, 256>>>(h1, b1, P, NN);
    k_zero4<<<2048, 256>>>(h2, NN * 128 / 4);
    k_edge128<<<edgeBlocks, 256>>>(P, src, dst, c1, nrm, h2);

    // layer 2: relu(h2) -> out (no final activation)
    k_gemm<64, true><<<gemmGrid, 256>>>(h2, b2, P, NN);
    k_zero4<<<2048, 256>>>(out, NN * 64 / 4);
    k_edge64<<<edgeBlocks, 256>>>(P, src, dst, c2, nrm, out);
}

// round 3
// speedup vs baseline: 1.7510x; 1.5010x over previous
#include <cuda_runtime.h>
#include <cuda_fp16.h>

#define NN 50000
#define RR 4
#define EE 400000
#define NR (RR * NN)          // 200000 (node,relation) pairs
#define NB1 ((NR + 1023) / 1024)

// ---- scratch (static __device__; no allocation) ----
__device__ __half g_h[NN * 128];     // current layer input features (fp16)
__device__ __half g_G[NN * 256];     // aggregated features [G0 | G1] (fp16)
__device__ int    g_deg [2 * NR];    // [out:4][N] then [in:4][N]
__device__ float  g_norm[2 * NR];    // rsqrt(max(deg,1)) same layout
__device__ int    g_off[NR + 1];     // CSR offsets (by r*NN+dst)
__device__ int    g_cur[NR];         // fill cursors
__device__ int2   g_epk[RR * EE];    // packed edge: {src, bitcast(n_out[r][src])}
__device__ int    g_bsum[256];       // block sums for scan

// ---------------- degree / norm ----------------
__global__ void k_zerodeg() {
    int i = blockIdx.x * blockDim.x + threadIdx.x;
    if (i < 2 * NR) g_deg[i] = 0;
}

__global__ void k_count(const int* __restrict__ src, const int* __restrict__ dst) {
    int i = blockIdx.x * blockDim.x + threadIdx.x;
    if (i >= RR * EE) return;
    int r = i / EE;
    atomicAdd(&g_deg[r * NN + src[i]], 1);        // out-degree
    atomicAdd(&g_deg[NR + r * NN + dst[i]], 1);   // in-degree
}

__global__ void k_norm() {
    int i = blockIdx.x * blockDim.x + threadIdx.x;
    if (i < 2 * NR) {
        int d = g_deg[i];
        if (d < 1) d = 1;
        g_norm[i] = rsqrtf((float)d);
    }
}

// ---------------- CSR build (counting sort by dst) ----------------
__global__ void k_scan1() {   // per-1024-block sums of in-degree
    __shared__ int sh[1024];
    int i = blockIdx.x * 1024 + threadIdx.x;
    sh[threadIdx.x] = (i < NR) ? g_deg[NR + i] : 0;
    __syncthreads();
    for (int s = 512; s > 0; s >>= 1) {
        if (threadIdx.x < s) sh[threadIdx.x] += sh[threadIdx.x + s];
        __syncthreads();
    }
    if (threadIdx.x == 0) g_bsum[blockIdx.x] = sh[0];
}

__global__ void k_scan2() {   // exclusive scan of block sums (single block)
    __shared__ int sh[256];
    int t = threadIdx.x;
    sh[t] = (t < NB1) ? g_bsum[t] : 0;
    __syncthreads();
    for (int s = 1; s < 256; s <<= 1) {
        int v = (t >= s) ? sh[t - s] : 0;
        __syncthreads();
        sh[t] += v;
        __syncthreads();
    }
    if (t < NB1) g_bsum[t] = (t == 0) ? 0 : sh[t - 1];
}

__global__ void k_scan3() {   // final offsets + cursors
    __shared__ int sh[1024];
    int i = blockIdx.x * 1024 + threadIdx.x;
    int v = (i < NR) ? g_deg[NR + i] : 0;
    sh[threadIdx.x] = v;
    __syncthreads();
    for (int s = 1; s < 1024; s <<= 1) {
        int u = (threadIdx.x >= s) ? sh[threadIdx.x - s] : 0;
        __syncthreads();
        sh[threadIdx.x] += u;
        __syncthreads();
    }
    if (i < NR) {
        int ex = g_bsum[blockIdx.x] + sh[threadIdx.x] - v;
        g_off[i] = ex;
        g_cur[i] = ex;
    }
    if (i == NR - 1) g_off[NR] = g_bsum[blockIdx.x] + sh[threadIdx.x];
}

__global__ void k_fill(const int* __restrict__ src, const int* __restrict__ dst) {
    int i = blockIdx.x * blockDim.x + threadIdx.x;
    if (i >= RR * EE) return;
    int r = i / EE;
    int s = src[i], d = dst[i];
    int pos = atomicAdd(&g_cur[r * NN + d], 1);
    int2 p;
    p.x = s;
    p.y = __float_as_int(g_norm[r * NN + s]);   // n_out[r][s]
    g_epk[pos] = p;
}

// ---------------- x -> fp16 ----------------
__global__ void k_cvt(const float* __restrict__ x) {
    int i = blockIdx.x * blockDim.x + threadIdx.x;
    if (i < NN * 128) g_h[i] = __float2half(x[i]);
}

// ---------------- aggregation: h -> G (warp per node, no atomics) ----------------
__device__ __forceinline__ void accA(float4& acc, uint2 pk, float we) {
    float2 f0 = __half22float2(*(__half2*)&pk.x);
    float2 f1 = __half22float2(*(__half2*)&pk.y);
    acc.x = fmaf(we, f0.x, acc.x);
    acc.y = fmaf(we, f0.y, acc.y);
    acc.z = fmaf(we, f1.x, acc.z);
    acc.w = fmaf(we, f1.y, acc.w);
}

__global__ void __launch_bounds__(256)
k_agg(const __half* __restrict__ h, const float* __restrict__ coeff,
      __half* __restrict__ G) {
    int w = (blockIdx.x * 256 + threadIdx.x) >> 5;   // node id
    int lane = threadIdx.x & 31;
    if (w >= NN) return;
    float4 g0 = make_float4(0.f, 0.f, 0.f, 0.f);
    float4 g1 = make_float4(0.f, 0.f, 0.f, 0.f);
#pragma unroll
    for (int r = 0; r < RR; r++) {
        int idx = r * NN + w;
        int beg = g_off[idx], end = g_off[idx + 1];
        float4 acc = make_float4(0.f, 0.f, 0.f, 0.f);
        int e = beg;
        for (; e + 2 <= end; e += 2) {                 // 2-way pipelined gather
            int2 p0 = g_epk[e], p1 = g_epk[e + 1];
            uint2 a = ((const uint2*)(h + p0.x * 128))[lane];
            uint2 b = ((const uint2*)(h + p1.x * 128))[lane];
            accA(acc, a, __int_as_float(p0.y));
            accA(acc, b, __int_as_float(p1.y));
        }
        if (e < end) {
            int2 p = g_epk[e];
            uint2 a = ((const uint2*)(h + p.x * 128))[lane];
            accA(acc, a, __int_as_float(p.y));
        }
        float ni = g_norm[NR + idx];                   // n_in[r][w]
        float s0 = ni * coeff[2 * r];
        float s1 = ni * coeff[2 * r + 1];
        g0.x = fmaf(s0, acc.x, g0.x); g0.y = fmaf(s0, acc.y, g0.y);
        g0.z = fmaf(s0, acc.z, g0.z); g0.w = fmaf(s0, acc.w, g0.w);
        g1.x = fmaf(s1, acc.x, g1.x); g1.y = fmaf(s1, acc.y, g1.y);
        g1.z = fmaf(s1, acc.z, g1.z); g1.w = fmaf(s1, acc.w, g1.w);
    }
    __half2 a0 = __floats2half2_rn(g0.x, g0.y), a1 = __floats2half2_rn(g0.z, g0.w);
    __half2 b0 = __floats2half2_rn(g1.x, g1.y), b1 = __floats2half2_rn(g1.z, g1.w);
    uint2 u0, u1;
    u0.x = *(unsigned*)&a0; u0.y = *(unsigned*)&a1;
    u1.x = *(unsigned*)&b0; u1.y = *(unsigned*)&b1;
    ((uint2*)(G + w * 256))[lane]       = u0;   // G0 half[lane*4]
    ((uint2*)(G + w * 256 + 128))[lane] = u1;   // G1
}

// ---------------- GEMM: G[N,256] @ [B0;B1] -> h_next / out ----------------
// Bmat layout: basis (2, 128, DO): row kk -> basis[kk>>7][kk&127][o]
template<int DO, bool RELU, bool TOHALF>
__global__ void __launch_bounds__(256)
k_gemm(const __half* __restrict__ G, const float* __restrict__ Bmat,
       void* __restrict__ outp) {
    const int NJ = DO / 32;
    __shared__ float As[64][33];
    __shared__ float Bs[32 * DO];

    int row0 = blockIdx.x * 64;
    int tid = threadIdx.x;
    int tx = tid & 31;
    int ty = tid >> 5;

    float acc[8][NJ];
#pragma unroll
    for (int i = 0; i < 8; i++)
#pragma unroll
        for (int j = 0; j < NJ; j++) acc[i][j] = 0.f;

    for (int k0 = 0; k0 < 256; k0 += 32) {
#pragma unroll
        for (int idx = tid; idx < 64 * 32; idx += 256) {
            int r = idx >> 5, k = idx & 31;
            int row = row0 + r;
            As[r][k] = (row < NN) ? __half2float(G[row * 256 + k0 + k]) : 0.f;
        }
#pragma unroll
        for (int idx = tid; idx < 32 * DO; idx += 256) {
            int k = idx / DO, c = idx % DO;
            int kk = k0 + k;
            Bs[idx] = Bmat[((kk >> 7) * 128 + (kk & 127)) * DO + c];
        }
        __syncthreads();
#pragma unroll 8
        for (int k = 0; k < 32; k++) {
            float a[8];
#pragma unroll
            for (int i = 0; i < 8; i++) a[i] = As[ty + 8 * i][k];
#pragma unroll
            for (int j = 0; j < NJ; j++) {
                float b = Bs[k * DO + tx + 32 * j];
#pragma unroll
                for (int i = 0; i < 8; i++) acc[i][j] = fmaf(a[i], b, acc[i][j]);
            }
        }
        __syncthreads();
    }
#pragma unroll
    for (int i = 0; i < 8; i++) {
        int row = row0 + ty + 8 * i;
        if (row < NN) {
#pragma unroll
            for (int j = 0; j < NJ; j++) {
                float v = acc[i][j];
                if (RELU) v = fmaxf(v, 0.f);
                if (TOHALF)
                    ((__half*)outp)[row * DO + tx + 32 * j] = __float2half(v);
                else
                    ((float*)outp)[row * DO + tx + 32 * j] = v;
            }
        }
    }
}

// ---------------- launch ----------------
extern "C" void kernel_launch(void* const* d_in, const int* in_sizes, int n_in,
                              void* d_out, int out_size) {
    const float* x   = (const float*)d_in[0];
    const int*   src = (const int*)  d_in[1];
    const int*   dst = (const int*)  d_in[2];
    const float* b0  = (const float*)d_in[3];
    const float* c0  = (const float*)d_in[4];
    const float* b1  = (const float*)d_in[5];
    const float* c1  = (const float*)d_in[6];
    const float* b2  = (const float*)d_in[7];
    const float* c2  = (const float*)d_in[8];
    float* out = (float*)d_out;

    __half *h, *G;
    cudaGetSymbolAddress((void**)&h, g_h);
    cudaGetSymbolAddress((void**)&G, g_G);

    const int edgeTh  = (RR * EE + 255) / 256;
    const int aggGrid = (NN * 32 + 255) / 256;
    const int gemmGrid = (NN + 63) / 64;

    // graph preprocessing (every call: deterministic)
    k_zerodeg<<<(2 * NR + 255) / 256, 256>>>();
    k_count<<<edgeTh, 256>>>(src, dst);
    k_norm<<<(2 * NR + 255) / 256, 256>>>();
    k_scan1<<<NB1, 1024>>>();
    k_scan2<<<1, 256>>>();
    k_scan3<<<NB1, 1024>>>();
    k_fill<<<edgeTh, 256>>>(src, dst);
    k_cvt<<<(NN * 128 + 255) / 256, 256>>>(x);

    // layer 0: x -> h (relu, fp16)
    k_agg<<<aggGrid, 256>>>(h, c0, G);
    k_gemm<128, true, true><<<gemmGrid, 256>>>(G, b0, h);
    // layer 1
    k_agg<<<aggGrid, 256>>>(h, c1, G);
    k_gemm<128, true, true><<<gemmGrid, 256>>>(G, b1, h);
    // layer 2: final, fp32, no relu
    k_agg<<<aggGrid, 256>>>(h, c2, G);
    k_gemm<64, false, false><<<gemmGrid, 256>>>(G, b2, out);
}

// round 4
// speedup vs baseline: 2.9085x; 1.6611x over previous
#include <cuda_runtime.h>
#include <cuda_fp16.h>

#define NN 50000
#define RR 4
#define EE 400000
#define NR (RR * NN)          // 200000 (node,relation) pairs
#define NB1 ((NR + 1023) / 1024)

// ---- scratch (static __device__; no allocation) ----
__device__ __half g_h[NN * 128];     // current layer input features (fp16)
__device__ __half g_G[NN * 256];     // aggregated features [G0 | G1] (fp16)
__device__ __half g_Bh[(128 + 128 + 64) * 264];  // fp16 weights, [DO][264] n-major
__device__ int    g_deg [2 * NR];    // [out:4][N] then [in:4][N]
__device__ float  g_norm[2 * NR];    // rsqrt(max(deg,1)) same layout
__device__ int    g_off[NR + 1];     // CSR offsets (by r*NN+dst)
__device__ int    g_cur[NR];         // fill cursors
__device__ int2   g_epk[RR * EE];    // packed edge: {src, bitcast(n_out[r][src])}
__device__ int    g_bsum[256];       // block sums for scan

// ---------------- degree / norm ----------------
__global__ void k_zerodeg() {
    int i = blockIdx.x * blockDim.x + threadIdx.x;
    if (i < 2 * NR) g_deg[i] = 0;
}

__global__ void k_count(const int* __restrict__ src, const int* __restrict__ dst) {
    int i = blockIdx.x * blockDim.x + threadIdx.x;
    if (i >= RR * EE) return;
    int r = i / EE;
    atomicAdd(&g_deg[r * NN + src[i]], 1);        // out-degree
    atomicAdd(&g_deg[NR + r * NN + dst[i]], 1);   // in-degree
}

__global__ void k_norm() {
    int i = blockIdx.x * blockDim.x + threadIdx.x;
    if (i < 2 * NR) {
        int d = g_deg[i];
        if (d < 1) d = 1;
        g_norm[i] = rsqrtf((float)d);
    }
}

// ---------------- CSR build (counting sort by dst) ----------------
__global__ void k_scan1() {
    __shared__ int sh[1024];
    int i = blockIdx.x * 1024 + threadIdx.x;
    sh[threadIdx.x] = (i < NR) ? g_deg[NR + i] : 0;
    __syncthreads();
    for (int s = 512; s > 0; s >>= 1) {
        if (threadIdx.x < s) sh[threadIdx.x] += sh[threadIdx.x + s];
        __syncthreads();
    }
    if (threadIdx.x == 0) g_bsum[blockIdx.x] = sh[0];
}

__global__ void k_scan2() {
    __shared__ int sh[256];
    int t = threadIdx.x;
    sh[t] = (t < NB1) ? g_bsum[t] : 0;
    __syncthreads();
    for (int s = 1; s < 256; s <<= 1) {
        int v = (t >= s) ? sh[t - s] : 0;
        __syncthreads();
        sh[t] += v;
        __syncthreads();
    }
    if (t < NB1) g_bsum[t] = (t == 0) ? 0 : sh[t - 1];
}

__global__ void k_scan3() {
    __shared__ int sh[1024];
    int i = blockIdx.x * 1024 + threadIdx.x;
    int v = (i < NR) ? g_deg[NR + i] : 0;
    sh[threadIdx.x] = v;
    __syncthreads();
    for (int s = 1; s < 1024; s <<= 1) {
        int u = (threadIdx.x >= s) ? sh[threadIdx.x - s] : 0;
        __syncthreads();
        sh[threadIdx.x] += u;
        __syncthreads();
    }
    if (i < NR) {
        int ex = g_bsum[blockIdx.x] + sh[threadIdx.x] - v;
        g_off[i] = ex;
        g_cur[i] = ex;
    }
    if (i == NR - 1) g_off[NR] = g_bsum[blockIdx.x] + sh[threadIdx.x];
}

__global__ void k_fill(const int* __restrict__ src, const int* __restrict__ dst) {
    int i = blockIdx.x * blockDim.x + threadIdx.x;
    if (i >= RR * EE) return;
    int r = i / EE;
    int s = src[i], d = dst[i];
    int pos = atomicAdd(&g_cur[r * NN + d], 1);
    int2 p;
    p.x = s;
    p.y = __float_as_int(g_norm[r * NN + s]);
    g_epk[pos] = p;
}

// ---------------- conversions ----------------
__global__ void k_cvt(const float* __restrict__ x) {
    int i = blockIdx.x * blockDim.x + threadIdx.x;
    if (i < NN * 128) g_h[i] = __float2half(x[i]);
}

// fp32 basis (2,128,DO) -> fp16 [n][kk] with row stride 264
__global__ void k_bcvt(const float* __restrict__ B, __half* __restrict__ o, int DOw) {
    int i = blockIdx.x * blockDim.x + threadIdx.x;
    if (i >= DOw * 256) return;
    int n = i >> 8, kk = i & 255;
    o[n * 264 + kk] = __float2half(B[((kk >> 7) * 128 + (kk & 127)) * DOw + n]);
}

// ---------------- aggregation: h -> G (warp per node, no atomics) ----------------
__device__ __forceinline__ void accA(float4& acc, uint2 pk, float we) {
    float2 f0 = __half22float2(*(__half2*)&pk.x);
    float2 f1 = __half22float2(*(__half2*)&pk.y);
    acc.x = fmaf(we, f0.x, acc.x);
    acc.y = fmaf(we, f0.y, acc.y);
    acc.z = fmaf(we, f1.x, acc.z);
    acc.w = fmaf(we, f1.y, acc.w);
}

__global__ void __launch_bounds__(256)
k_agg(const __half* __restrict__ h, const float* __restrict__ coeff,
      __half* __restrict__ G) {
    int w = (blockIdx.x * 256 + threadIdx.x) >> 5;
    int lane = threadIdx.x & 31;
    if (w >= NN) return;
    float4 g0 = make_float4(0.f, 0.f, 0.f, 0.f);
    float4 g1 = make_float4(0.f, 0.f, 0.f, 0.f);
#pragma unroll
    for (int r = 0; r < RR; r++) {
        int idx = r * NN + w;
        int beg = g_off[idx], end = g_off[idx + 1];
        float4 acc = make_float4(0.f, 0.f, 0.f, 0.f);
        int e = beg;
        for (; e + 2 <= end; e += 2) {
            int2 p0 = g_epk[e], p1 = g_epk[e + 1];
            uint2 a = ((const uint2*)(h + p0.x * 128))[lane];
            uint2 b = ((const uint2*)(h + p1.x * 128))[lane];
            accA(acc, a, __int_as_float(p0.y));
            accA(acc, b, __int_as_float(p1.y));
        }
        if (e < end) {
            int2 p = g_epk[e];
            uint2 a = ((const uint2*)(h + p.x * 128))[lane];
            accA(acc, a, __int_as_float(p.y));
        }
        float ni = g_norm[NR + idx];
        float s0 = ni * coeff[2 * r];
        float s1 = ni * coeff[2 * r + 1];
        g0.x = fmaf(s0, acc.x, g0.x); g0.y = fmaf(s0, acc.y, g0.y);
        g0.z = fmaf(s0, acc.z, g0.z); g0.w = fmaf(s0, acc.w, g0.w);
        g1.x = fmaf(s1, acc.x, g1.x); g1.y = fmaf(s1, acc.y, g1.y);
        g1.z = fmaf(s1, acc.z, g1.z); g1.w = fmaf(s1, acc.w, g1.w);
    }
    __half2 a0 = __floats2half2_rn(g0.x, g0.y), a1 = __floats2half2_rn(g0.z, g0.w);
    __half2 b0 = __floats2half2_rn(g1.x, g1.y), b1 = __floats2half2_rn(g1.z, g1.w);
    uint2 u0, u1;
    u0.x = *(unsigned*)&a0; u0.y = *(unsigned*)&a1;
    u1.x = *(unsigned*)&b0; u1.y = *(unsigned*)&b1;
    ((uint2*)(G + w * 256))[lane]       = u0;
    ((uint2*)(G + w * 256 + 128))[lane] = u1;
}

// ---------------- tensor-core GEMM: G[N,256](fp16) @ B -> out ----------------
// block: 128 rows (8 warps x 16) x 64 cols (blockIdx.y); K=256 in 16 steps.
template<int DO, bool RELU, bool TOHALF>
__global__ void __launch_bounds__(256)
k_gemm_tc(const __half* __restrict__ G, const __half* __restrict__ Bh,
          void* __restrict__ outp) {
    __shared__ __half Bs[64 * 264];   // [n][k], stride 264 halves
    __shared__ __half As[128 * 24];   // [row][k-chunk16], stride 24 halves

    int tid  = threadIdx.x;
    int warp = tid >> 5, lane = tid & 31;
    int row0 = blockIdx.x * 128;
    int col0 = blockIdx.y * 64;

    // load B slice (rows [col0, col0+64) of [DO][264]) contiguously
    const uint4* gB = (const uint4*)(Bh + col0 * 264);
    for (int i = tid; i < 64 * 33; i += 256)
        ((uint4*)Bs)[i] = gB[i];
    __syncthreads();

    float acc[8][4];
#pragma unroll
    for (int n = 0; n < 8; n++)
#pragma unroll
        for (int j = 0; j < 4; j++) acc[n][j] = 0.f;

    int arow = tid >> 1, aseg = tid & 1;
    int grow = row0 + arow;
    const __half* gA = G + grow * 256 + aseg * 8;
    __half* asd = As + arow * 24 + aseg * 8;
    bool aok = grow < NN;

    unsigned ald = (unsigned)__cvta_generic_to_shared(
        As + (warp * 16 + (lane & 15)) * 24 + (lane >> 4) * 8);
    int bn = lane >> 2, bk = (lane & 3) * 2;

    for (int ks = 0; ks < 16; ks++) {
        int k0 = ks * 16;
        uint4 v = make_uint4(0u, 0u, 0u, 0u);
        if (aok) v = *(const uint4*)(gA + k0);
        *(uint4*)asd = v;
        __syncthreads();

        unsigned a0, a1, a2, a3;
        asm volatile("ldmatrix.sync.aligned.m8n8.x4.shared.b16 {%0,%1,%2,%3}, [%4];"
                     : "=r"(a0), "=r"(a1), "=r"(a2), "=r"(a3) : "r"(ald));
#pragma unroll
        for (int nt = 0; nt < 8; nt++) {
            const __half* bp = Bs + (nt * 8 + bn) * 264 + k0 + bk;
            unsigned b0 = *(const unsigned*)bp;
            unsigned b1 = *(const unsigned*)(bp + 8);
            asm volatile(
                "mma.sync.aligned.m16n8k16.row.col.f32.f16.f16.f32 "
                "{%0,%1,%2,%3}, {%4,%5,%6,%7}, {%8,%9}, {%0,%1,%2,%3};"
                : "+f"(acc[nt][0]), "+f"(acc[nt][1]), "+f"(acc[nt][2]), "+f"(acc[nt][3])
                : "r"(a0), "r"(a1), "r"(a2), "r"(a3), "r"(b0), "r"(b1));
        }
        __syncthreads();
    }

    // epilogue: d0/d1 = (r, c, c+1); d2/d3 = (r+8, c, c+1)
    int rlo = row0 + warp * 16 + (lane >> 2);
    int cb  = col0 + (lane & 3) * 2;
#pragma unroll
    for (int nt = 0; nt < 8; nt++) {
        int c = cb + nt * 8;
        float d0 = acc[nt][0], d1 = acc[nt][1], d2 = acc[nt][2], d3 = acc[nt][3];
        if (RELU) {
            d0 = fmaxf(d0, 0.f); d1 = fmaxf(d1, 0.f);
            d2 = fmaxf(d2, 0.f); d3 = fmaxf(d3, 0.f);
        }
        if (TOHALF) {
            __half* o = (__half*)outp;
            if (rlo < NN)     *(__half2*)(o + rlo * DO + c)       = __floats2half2_rn(d0, d1);
            if (rlo + 8 < NN) *(__half2*)(o + (rlo + 8) * DO + c) = __floats2half2_rn(d2, d3);
        } else {
            float* o = (float*)outp;
            if (rlo < NN)     { o[rlo * DO + c] = d0;       o[rlo * DO + c + 1] = d1; }
            if (rlo + 8 < NN) { o[(rlo + 8) * DO + c] = d2; o[(rlo + 8) * DO + c + 1] = d3; }
        }
    }
}

// ---------------- launch ----------------
extern "C" void kernel_launch(void* const* d_in, const int* in_sizes, int n_in,
                              void* d_out, int out_size) {
    const float* x   = (const float*)d_in[0];
    const int*   src = (const int*)  d_in[1];
    const int*   dst = (const int*)  d_in[2];
    const float* b0  = (const float*)d_in[3];
    const float* c0  = (const float*)d_in[4];
    const float* b1  = (const float*)d_in[5];
    const float* c1  = (const float*)d_in[6];
    const float* b2  = (const float*)d_in[7];
    const float* c2  = (const float*)d_in[8];
    float* out = (float*)d_out;

    __half *h, *G, *Bh;
    cudaGetSymbolAddress((void**)&h,  g_h);
    cudaGetSymbolAddress((void**)&G,  g_G);
    cudaGetSymbolAddress((void**)&Bh, g_Bh);
    __half* Bh0 = Bh;
    __half* Bh1 = Bh + 128 * 264;
    __half* Bh2 = Bh + 256 * 264;

    const int edgeTh  = (RR * EE + 255) / 256;
    const int aggGrid = (NN * 32 + 255) / 256;
    const dim3 gemm2(391, 2), gemm1(391, 1);

    // graph preprocessing (every call: deterministic)
    k_zerodeg<<<(2 * NR + 255) / 256, 256>>>();
    k_count<<<edgeTh, 256>>>(src, dst);
    k_norm<<<(2 * NR + 255) / 256, 256>>>();
    k_scan1<<<NB1, 1024>>>();
    k_scan2<<<1, 256>>>();
    k_scan3<<<NB1, 1024>>>();
    k_fill<<<edgeTh, 256>>>(src, dst);
    k_cvt<<<(NN * 128 + 255) / 256, 256>>>(x);
    k_bcvt<<<(128 * 256 + 255) / 256, 256>>>(b0, Bh0, 128);
    k_bcvt<<<(128 * 256 + 255) / 256, 256>>>(b1, Bh1, 128);
    k_bcvt<<<(64 * 256 + 255) / 256, 256>>>(b2, Bh2, 64);

    // layer 0
    k_agg<<<aggGrid, 256>>>(h, c0, G);
    k_gemm_tc<128, true, true><<<gemm2, 256>>>(G, Bh0, h);
    // layer 1
    k_agg<<<aggGrid, 256>>>(h, c1, G);
    k_gemm_tc<128, true, true><<<gemm2, 256>>>(G, Bh1, h);
    // layer 2: final, fp32, no relu
    k_agg<<<aggGrid, 256>>>(h, c2, G);
    k_gemm_tc<64, false, false><<<gemm1, 256>>>(G, Bh2, out);
}

// round 5
// speedup vs baseline: 2.9683x; 1.0206x over previous
#include <cuda_runtime.h>
#include <cuda_fp16.h>

#define NN 50000
#define RR 4
#define EE 400000
#define NR (RR * NN)          // 200000 (node,relation) pairs
#define NB1 ((NR + 1023) / 1024)

// ---- scratch (static __device__; no allocation) ----
__device__ __half g_h[NN * 128];     // current layer input features (fp16)
__device__ __half g_G[NN * 256];     // aggregated features [G0 | G1] (fp16)
__device__ __half g_Bh[(128 + 128 + 64) * 264];  // fp16 weights, [DO][264] n-major
__device__ int    g_deg [2 * NR];    // [out:4][N] then [in:4][N]
__device__ float  g_norm[2 * NR];    // rsqrt(max(deg,1)) same layout
__device__ int    g_off[NR + 1];     // CSR offsets (by r*NN+dst)
__device__ int    g_cur[NR];         // fill cursors
__device__ int2   g_epk[RR * EE];    // packed edge: {src, bitcast(n_out[r][src])}
__device__ int    g_bsum[256];       // block sums for scan

// ---------------- degree / norm ----------------
__global__ void k_zerodeg() {
    int i = blockIdx.x * blockDim.x + threadIdx.x;
    if (i < 2 * NR) g_deg[i] = 0;
}

__global__ void k_count(const int* __restrict__ src, const int* __restrict__ dst) {
    int i = blockIdx.x * blockDim.x + threadIdx.x;
    if (i >= RR * EE) return;
    int r = i / EE;
    atomicAdd(&g_deg[r * NN + src[i]], 1);        // out-degree
    atomicAdd(&g_deg[NR + r * NN + dst[i]], 1);   // in-degree
}

__global__ void k_norm() {
    int i = blockIdx.x * blockDim.x + threadIdx.x;
    if (i < 2 * NR) {
        int d = g_deg[i];
        if (d < 1) d = 1;
        g_norm[i] = rsqrtf((float)d);
    }
}

// ---------------- CSR build (counting sort by dst) ----------------
__global__ void k_scan1() {
    __shared__ int sh[1024];
    int i = blockIdx.x * 1024 + threadIdx.x;
    sh[threadIdx.x] = (i < NR) ? g_deg[NR + i] : 0;
    __syncthreads();
    for (int s = 512; s > 0; s >>= 1) {
        if (threadIdx.x < s) sh[threadIdx.x] += sh[threadIdx.x + s];
        __syncthreads();
    }
    if (threadIdx.x == 0) g_bsum[blockIdx.x] = sh[0];
}

__global__ void k_scan2() {
    __shared__ int sh[256];
    int t = threadIdx.x;
    sh[t] = (t < NB1) ? g_bsum[t] : 0;
    __syncthreads();
    for (int s = 1; s < 256; s <<= 1) {
        int v = (t >= s) ? sh[t - s] : 0;
        __syncthreads();
        sh[t] += v;
        __syncthreads();
    }
    if (t < NB1) g_bsum[t] = (t == 0) ? 0 : sh[t - 1];
}

__global__ void k_scan3() {
    __shared__ int sh[1024];
    int i = blockIdx.x * 1024 + threadIdx.x;
    int v = (i < NR) ? g_deg[NR + i] : 0;
    sh[threadIdx.x] = v;
    __syncthreads();
    for (int s = 1; s < 1024; s <<= 1) {
        int u = (threadIdx.x >= s) ? sh[threadIdx.x - s] : 0;
        __syncthreads();
        sh[threadIdx.x] += u;
        __syncthreads();
    }
    if (i < NR) {
        int ex = g_bsum[blockIdx.x] + sh[threadIdx.x] - v;
        g_off[i] = ex;
        g_cur[i] = ex;
    }
    if (i == NR - 1) g_off[NR] = g_bsum[blockIdx.x] + sh[threadIdx.x];
}

__global__ void k_fill(const int* __restrict__ src, const int* __restrict__ dst) {
    int i = blockIdx.x * blockDim.x + threadIdx.x;
    if (i >= RR * EE) return;
    int r = i / EE;
    int s = src[i], d = dst[i];
    int pos = atomicAdd(&g_cur[r * NN + d], 1);
    int2 p;
    p.x = s;
    p.y = __float_as_int(g_norm[r * NN + s]);
    g_epk[pos] = p;
}

// ---------------- conversions ----------------
__global__ void k_cvt(const float* __restrict__ x) {
    int i = blockIdx.x * blockDim.x + threadIdx.x;
    if (i < NN * 128) g_h[i] = __float2half(x[i]);
}

// fp32 basis (2,128,DO) -> fp16 [n][kk] with row stride 264
__global__ void k_bcvt(const float* __restrict__ B, __half* __restrict__ o, int DOw) {
    int i = blockIdx.x * blockDim.x + threadIdx.x;
    if (i >= DOw * 256) return;
    int n = i >> 8, kk = i & 255;
    o[n * 264 + kk] = __float2half(B[((kk >> 7) * 128 + (kk & 127)) * DOw + n]);
}

// ---------------- aggregation: h -> G (warp per node, no atomics) ----------------
__device__ __forceinline__ void accA(float4& acc, uint2 pk, float we) {
    float2 f0 = __half22float2(*(__half2*)&pk.x);
    float2 f1 = __half22float2(*(__half2*)&pk.y);
    acc.x = fmaf(we, f0.x, acc.x);
    acc.y = fmaf(we, f0.y, acc.y);
    acc.z = fmaf(we, f1.x, acc.z);
    acc.w = fmaf(we, f1.y, acc.w);
}

__global__ void __launch_bounds__(256)
k_agg(const __half* __restrict__ h, const float* __restrict__ coeff,
      __half* __restrict__ G) {
    int w = (blockIdx.x * 256 + threadIdx.x) >> 5;
    int lane = threadIdx.x & 31;
    if (w >= NN) return;
    float4 g0 = make_float4(0.f, 0.f, 0.f, 0.f);
    float4 g1 = make_float4(0.f, 0.f, 0.f, 0.f);
#pragma unroll
    for (int r = 0; r < RR; r++) {
        int idx = r * NN + w;
        int beg = g_off[idx], end = g_off[idx + 1];
        float4 acc = make_float4(0.f, 0.f, 0.f, 0.f);
        int e = beg;
        for (; e + 2 <= end; e += 2) {
            int2 p0 = g_epk[e], p1 = g_epk[e + 1];
            uint2 a = ((const uint2*)(h + p0.x * 128))[lane];
            uint2 b = ((const uint2*)(h + p1.x * 128))[lane];
            accA(acc, a, __int_as_float(p0.y));
            accA(acc, b, __int_as_float(p1.y));
        }
        if (e < end) {
            int2 p = g_epk[e];
            uint2 a = ((const uint2*)(h + p.x * 128))[lane];
            accA(acc, a, __int_as_float(p.y));
        }
        float ni = g_norm[NR + idx];
        float s0 = ni * coeff[2 * r];
        float s1 = ni * coeff[2 * r + 1];
        g0.x = fmaf(s0, acc.x, g0.x); g0.y = fmaf(s0, acc.y, g0.y);
        g0.z = fmaf(s0, acc.z, g0.z); g0.w = fmaf(s0, acc.w, g0.w);
        g1.x = fmaf(s1, acc.x, g1.x); g1.y = fmaf(s1, acc.y, g1.y);
        g1.z = fmaf(s1, acc.z, g1.z); g1.w = fmaf(s1, acc.w, g1.w);
    }
    __half2 a0 = __floats2half2_rn(g0.x, g0.y), a1 = __floats2half2_rn(g0.z, g0.w);
    __half2 b0 = __floats2half2_rn(g1.x, g1.y), b1 = __floats2half2_rn(g1.z, g1.w);
    uint2 u0, u1;
    u0.x = *(unsigned*)&a0; u0.y = *(unsigned*)&a1;
    u1.x = *(unsigned*)&b0; u1.y = *(unsigned*)&b1;
    ((uint2*)(G + w * 256))[lane]       = u0;
    ((uint2*)(G + w * 256 + 128))[lane] = u1;
}

// ---------------- tensor-core GEMM: G[N,256](fp16) @ B -> out ----------------
// block: 128 rows (8 warps x 16) x 64 cols (blockIdx.y); K=256 in 16 steps.
template<int DO, bool RELU, bool TOHALF>
__global__ void __launch_bounds__(256)
k_gemm_tc(const __half* __restrict__ G, const __half* __restrict__ Bh,
          void* __restrict__ outp) {
    __shared__ __half Bs[64 * 264];   // [n][k], stride 264 halves
    __shared__ __half As[128 * 24];   // [row][k-chunk16], stride 24 halves

    int tid  = threadIdx.x;
    int warp = tid >> 5, lane = tid & 31;
    int row0 = blockIdx.x * 128;
    int col0 = blockIdx.y * 64;

    // load B slice (rows [col0, col0+64) of [DO][264]) contiguously
    const uint4* gB = (const uint4*)(Bh + col0 * 264);
    for (int i = tid; i < 64 * 33; i += 256)
        ((uint4*)Bs)[i] = gB[i];
    __syncthreads();

    float acc[8][4];
#pragma unroll
    for (int n = 0; n < 8; n++)
#pragma unroll
        for (int j = 0; j < 4; j++) acc[n][j] = 0.f;

    int arow = tid >> 1, aseg = tid & 1;
    int grow = row0 + arow;
    const __half* gA = G + grow * 256 + aseg * 8;
    __half* asd = As + arow * 24 + aseg * 8;
    bool aok = grow < NN;

    unsigned ald = (unsigned)__cvta_generic_to_shared(
        As + (warp * 16 + (lane & 15)) * 24 + (lane >> 4) * 8);
    int bn = lane >> 2, bk = (lane & 3) * 2;

    for (int ks = 0; ks < 16; ks++) {
        int k0 = ks * 16;
        uint4 v = make_uint4(0u, 0u, 0u, 0u);
        if (aok) v = *(const uint4*)(gA + k0);
        *(uint4*)asd = v;
        __syncthreads();

        unsigned a0, a1, a2, a3;
        asm volatile("ldmatrix.sync.aligned.m8n8.x4.shared.b16 {%0,%1,%2,%3}, [%4];"
                     : "=r"(a0), "=r"(a1), "=r"(a2), "=r"(a3) : "r"(ald));
#pragma unroll
        for (int nt = 0; nt < 8; nt++) {
            const __half* bp = Bs + (nt * 8 + bn) * 264 + k0 + bk;
            unsigned b0 = *(const unsigned*)bp;
            unsigned b1 = *(const unsigned*)(bp + 8);
            asm volatile(
                "mma.sync.aligned.m16n8k16.row.col.f32.f16.f16.f32 "
                "{%0,%1,%2,%3}, {%4,%5,%6,%7}, {%8,%9}, {%0,%1,%2,%3};"
                : "+f"(acc[nt][0]), "+f"(acc[nt][1]), "+f"(acc[nt][2]), "+f"(acc[nt][3])
                : "r"(a0), "r"(a1), "r"(a2), "r"(a3), "r"(b0), "r"(b1));
        }
        __syncthreads();
    }

    // epilogue: d0/d1 = (r, c, c+1); d2/d3 = (r+8, c, c+1)
    int rlo = row0 + warp * 16 + (lane >> 2);
    int cb  = col0 + (lane & 3) * 2;
#pragma unroll
    for (int nt = 0; nt < 8; nt++) {
        int c = cb + nt * 8;
        float d0 = acc[nt][0], d1 = acc[nt][1], d2 = acc[nt][2], d3 = acc[nt][3];
        if (RELU) {
            d0 = fmaxf(d0, 0.f); d1 = fmaxf(d1, 0.f);
            d2 = fmaxf(d2, 0.f); d3 = fmaxf(d3, 0.f);
        }
        if (TOHALF) {
            __half* o = (__half*)outp;
            if (rlo < NN)     *(__half2*)(o + rlo * DO + c)       = __floats2half2_rn(d0, d1);
            if (rlo + 8 < NN) *(__half2*)(o + (rlo + 8) * DO + c) = __floats2half2_rn(d2, d3);
        } else {
            float* o = (float*)outp;
            if (rlo < NN)     { o[rlo * DO + c] = d0;       o[rlo * DO + c + 1] = d1; }
            if (rlo + 8 < NN) { o[(rlo + 8) * DO + c] = d2; o[(rlo + 8) * DO + c + 1] = d3; }
        }
    }
}

// ---------------- launch ----------------
extern "C" void kernel_launch(void* const* d_in, const int* in_sizes, int n_in,
                              void* d_out, int out_size) {
    const float* x   = (const float*)d_in[0];
    const int*   src = (const int*)  d_in[1];
    const int*   dst = (const int*)  d_in[2];
    const float* b0  = (const float*)d_in[3];
    const float* c0  = (const float*)d_in[4];
    const float* b1  = (const float*)d_in[5];
    const float* c1  = (const float*)d_in[6];
    const float* b2  = (const float*)d_in[7];
    const float* c2  = (const float*)d_in[8];
    float* out = (float*)d_out;

    __half *h, *G, *Bh;
    cudaGetSymbolAddress((void**)&h,  g_h);
    cudaGetSymbolAddress((void**)&G,  g_G);
    cudaGetSymbolAddress((void**)&Bh, g_Bh);
    __half* Bh0 = Bh;
    __half* Bh1 = Bh + 128 * 264;
    __half* Bh2 = Bh + 256 * 264;

    const int edgeTh  = (RR * EE + 255) / 256;
    const int aggGrid = (NN * 32 + 255) / 256;
    const dim3 gemm2(391, 2), gemm1(391, 1);

    // graph preprocessing (every call: deterministic)
    k_zerodeg<<<(2 * NR + 255) / 256, 256>>>();
    k_count<<<edgeTh, 256>>>(src, dst);
    k_norm<<<(2 * NR + 255) / 256, 256>>>();
    k_scan1<<<NB1, 1024>>>();
    k_scan2<<<1, 256>>>();
    k_scan3<<<NB1, 1024>>>();
    k_fill<<<edgeTh, 256>>>(src, dst);
    k_cvt<<<(NN * 128 + 255) / 256, 256>>>(x);
    k_bcvt<<<(128 * 256 + 255) / 256, 256>>>(b0, Bh0, 128);
    k_bcvt<<<(128 * 256 + 255) / 256, 256>>>(b1, Bh1, 128);
    k_bcvt<<<(64 * 256 + 255) / 256, 256>>>(b2, Bh2, 64);

    // layer 0
    k_agg<<<aggGrid, 256>>>(h, c0, G);
    k_gemm_tc<128, true, true><<<gemm2, 256>>>(G, Bh0, h);
    // layer 1
    k_agg<<<aggGrid, 256>>>(h, c1, G);
    k_gemm_tc<128, true, true><<<gemm2, 256>>>(G, Bh1, h);
    // layer 2: final, fp32, no relu
    k_agg<<<aggGrid, 256>>>(h, c2, G);
    k_gemm_tc<64, false, false><<<gemm1, 256>>>(G, Bh2, out);
}